// round 16
// baseline (speedup 1.0000x reference)
#include <cuda_runtime.h>
#include <cuda_fp16.h>
#include <cstdint>

// ---------------- problem constants ----------------
#define K_DIM       2048
#define N_DIM       1024
#define ROWS_WHOLE  8192
#define ROWS_PARTS  32768
#define ROWS_TOTAL  40960
#define MB_WHOLE    64
#define MB_TOTAL    320

// ---------------- tile config ----------------
#define BM 128
#define BN 128
#define BK 32                      // k per stage (two m16n8k16 steps)
#define NCHUNK (K_DIM / BK)        // 64
#define SH 40                      // halves per smem row (80B stride, conflict-free)

#define TERM_B   (BM * SH * 2)     // 10240 bytes per term tile
#define AH0_B    0
#define AH1_B    (TERM_B)
#define BH0_B    (2 * TERM_B)
#define BH1_B    (3 * TERM_B)
#define STAGE_B  (4 * TERM_B)          // 40960 bytes per stage
#define BIAS_B   (2 * STAGE_B)         // 81920
#define SMEM_BYTES (BIAS_B + BN * 4)   // 82432

__device__ float g_sumsq[ROWS_TOTAL];

// ---------------- helpers ----------------
__device__ __forceinline__ void mma16(float* c,
                                      uint32_t a0, uint32_t a1, uint32_t a2, uint32_t a3,
                                      uint32_t b0, uint32_t b1) {
    asm volatile(
        "mma.sync.aligned.m16n8k16.row.col.f32.f16.f16.f32 "
        "{%0,%1,%2,%3}, {%4,%5,%6,%7}, {%8,%9}, {%0,%1,%2,%3};"
        : "+f"(c[0]), "+f"(c[1]), "+f"(c[2]), "+f"(c[3])
        : "r"(a0), "r"(a1), "r"(a2), "r"(a3), "r"(b0), "r"(b1));
}

// split 8 consecutive-k floats into packed fp16 h0 and residual h1
__device__ __forceinline__ void split8(float4 v0, float4 v1, uint4& H0, uint4& H1) {
    __half2 p0 = __floats2half2_rn(v0.x, v0.y);
    __half2 p1 = __floats2half2_rn(v0.z, v0.w);
    __half2 p2 = __floats2half2_rn(v1.x, v1.y);
    __half2 p3 = __floats2half2_rn(v1.z, v1.w);
    float2 q0 = __half22float2(p0);
    float2 q1 = __half22float2(p1);
    float2 q2 = __half22float2(p2);
    float2 q3 = __half22float2(p3);
    __half2 r0 = __floats2half2_rn(v0.x - q0.x, v0.y - q0.y);
    __half2 r1 = __floats2half2_rn(v0.z - q1.x, v0.w - q1.y);
    __half2 r2 = __floats2half2_rn(v1.x - q2.x, v1.y - q2.y);
    __half2 r3 = __floats2half2_rn(v1.z - q3.x, v1.w - q3.y);
    H0 = make_uint4(*(uint32_t*)&p0, *(uint32_t*)&p1, *(uint32_t*)&p2, *(uint32_t*)&p3);
    H1 = make_uint4(*(uint32_t*)&r0, *(uint32_t*)&r1, *(uint32_t*)&r2, *(uint32_t*)&r3);
}

__global__ void zero_kernel() {
    int i = blockIdx.x * 256 + threadIdx.x;
    if (i < ROWS_TOTAL) g_sumsq[i] = 0.0f;
}

// ---------------- merged fp16x2-split GEMM + row sum-of-squares (BK=32) ----------------
__global__ __launch_bounds__(256, 2)
void gemm_fp16x2_kernel(const float* __restrict__ Acur,
                        const float* __restrict__ Ahist,
                        const float* __restrict__ Ww,
                        const float* __restrict__ bw,
                        const float* __restrict__ Wp,
                        const float* __restrict__ bp)
{
    extern __shared__ __align__(16) char smem[];
    const int tid = threadIdx.x;
    const int wid = tid >> 5;
    const int lid = tid & 31;
    const int wm  = wid >> 2;
    const int wn  = wid & 3;
    const int r   = lid >> 2;
    const int cq  = lid & 3;
    const int by  = blockIdx.y;
    const int n0  = blockIdx.x * BN;

    const bool is_whole = (by < MB_WHOLE);
    const float* A    = is_whole ? Acur : Ahist;
    const float* W    = is_whole ? Ww   : Wp;
    const float* bias = is_whole ? bw   : bp;
    const int m0      = (is_whole ? by : (by - MB_WHOLE)) * BM;
    const int row_off = is_whole ? 0 : ROWS_WHOLE;

    float* sbias = (float*)(smem + BIAS_B);
    if (tid < BN) sbias[tid] = bias[n0 + tid];

    // loader coords: each thread handles 16 consecutive floats of one row
    const int ar  = tid >> 1;            // 0..127
    const int acf = (tid & 1) << 4;      // 0 or 16 (floats)
    const float* Aptr = A + (size_t)(m0 + ar) * K_DIM + acf;
    const float* Wptr = W + (size_t)(n0 + ar) * K_DIM + acf;
    const uint32_t s_off = (uint32_t)ar * (SH * 2) + (uint32_t)acf * 2;  // bytes

    float acc[4][4][4];
#pragma unroll
    for (int i = 0; i < 4; i++)
#pragma unroll
        for (int j = 0; j < 4; j++)
#pragma unroll
            for (int q = 0; q < 4; q++) acc[i][j][q] = 0.f;

    float4 av[4], bv[4];

#define LOADCHUNK(kc) do { \
        const float* ap_ = Aptr + (size_t)(kc) * BK; \
        av[0] = *(const float4*)ap_;       av[1] = *(const float4*)(ap_ + 4); \
        av[2] = *(const float4*)(ap_ + 8); av[3] = *(const float4*)(ap_ + 12); \
        const float* wp_ = Wptr + (size_t)(kc) * BK; \
        bv[0] = *(const float4*)wp_;       bv[1] = *(const float4*)(wp_ + 4); \
        bv[2] = *(const float4*)(wp_ + 8); bv[3] = *(const float4*)(wp_ + 12); \
    } while (0)

#define STORESTAGE(s) do { \
        char* st_ = smem + (s) * STAGE_B; \
        uint4 H0_, H1_; \
        split8(av[0], av[1], H0_, H1_); \
        *(uint4*)(st_ + AH0_B + s_off)      = H0_; \
        *(uint4*)(st_ + AH1_B + s_off)      = H1_; \
        split8(av[2], av[3], H0_, H1_); \
        *(uint4*)(st_ + AH0_B + s_off + 16) = H0_; \
        *(uint4*)(st_ + AH1_B + s_off + 16) = H1_; \
        split8(bv[0], bv[1], H0_, H1_); \
        *(uint4*)(st_ + BH0_B + s_off)      = H0_; \
        *(uint4*)(st_ + BH1_B + s_off)      = H1_; \
        split8(bv[2], bv[3], H0_, H1_); \
        *(uint4*)(st_ + BH0_B + s_off + 16) = H0_; \
        *(uint4*)(st_ + BH1_B + s_off + 16) = H1_; \
    } while (0)

    LOADCHUNK(0);
    STORESTAGE(0);
    LOADCHUNK(1);
    __syncthreads();

    for (int kc = 0; kc < NCHUNK; kc++) {
        const char* st = smem + (kc & 1) * STAGE_B;

#pragma unroll
        for (int ks = 0; ks < 2; ks++) {
            const int kb = ks * 32;   // byte offset of this k16 step within the row

            uint32_t b0h[4], b1h[4], b0l[4], b1l[4];
#pragma unroll
            for (int nf = 0; nf < 4; nf++) {
                const int off = (wn * 32 + nf * 8 + r) * (SH * 2) + kb + 4 * cq;
                b0h[nf] = *(const uint32_t*)(st + BH0_B + off);
                b1h[nf] = *(const uint32_t*)(st + BH0_B + off + 16);
                b0l[nf] = *(const uint32_t*)(st + BH1_B + off);
                b1l[nf] = *(const uint32_t*)(st + BH1_B + off + 16);
            }

#pragma unroll
            for (int mf = 0; mf < 4; mf++) {
                const int off0 = (wm * 64 + mf * 16 + r) * (SH * 2) + kb + 4 * cq;
                const int off1 = off0 + 8 * (SH * 2);
                uint32_t ah0 = *(const uint32_t*)(st + AH0_B + off0);
                uint32_t ah1 = *(const uint32_t*)(st + AH0_B + off1);
                uint32_t ah2 = *(const uint32_t*)(st + AH0_B + off0 + 16);
                uint32_t ah3 = *(const uint32_t*)(st + AH0_B + off1 + 16);
                uint32_t al0 = *(const uint32_t*)(st + AH1_B + off0);
                uint32_t al1 = *(const uint32_t*)(st + AH1_B + off1);
                uint32_t al2 = *(const uint32_t*)(st + AH1_B + off0 + 16);
                uint32_t al3 = *(const uint32_t*)(st + AH1_B + off1 + 16);
#pragma unroll
                for (int nf = 0; nf < 4; nf++) {
                    mma16(acc[mf][nf], ah0, ah1, ah2, ah3, b0h[nf], b1h[nf]);  // h0*h0
                    mma16(acc[mf][nf], ah0, ah1, ah2, ah3, b0l[nf], b1l[nf]);  // h0*h1
                    mma16(acc[mf][nf], al0, al1, al2, al3, b0h[nf], b1h[nf]);  // h1*h0
                }
            }
        }

        if (kc + 1 < NCHUNK) {
            STORESTAGE((kc + 1) & 1);
            if (kc + 2 < NCHUNK) LOADCHUNK(kc + 2);
        }
        __syncthreads();
    }

    // ---------------- epilogue: bias, square, per-row reduce, atomic ----------------
#pragma unroll
    for (int mf = 0; mf < 4; mf++) {
        float rs0 = 0.f, rs1 = 0.f;
#pragma unroll
        for (int nf = 0; nf < 4; nf++) {
            const int nc = wn * 32 + nf * 8 + 2 * cq;
            float b0 = sbias[nc], b1 = sbias[nc + 1];
            float v;
            v = acc[mf][nf][0] + b0; rs0 += v * v;
            v = acc[mf][nf][1] + b1; rs0 += v * v;
            v = acc[mf][nf][2] + b0; rs1 += v * v;
            v = acc[mf][nf][3] + b1; rs1 += v * v;
        }
        rs0 += __shfl_xor_sync(0xffffffffu, rs0, 1);
        rs0 += __shfl_xor_sync(0xffffffffu, rs0, 2);
        rs1 += __shfl_xor_sync(0xffffffffu, rs1, 1);
        rs1 += __shfl_xor_sync(0xffffffffu, rs1, 2);
        if (cq == 0) {
            const int mrow = row_off + m0 + wm * 64 + mf * 16 + r;
            atomicAdd(&g_sumsq[mrow],     rs0);
            atomicAdd(&g_sumsq[mrow + 8], rs1);
        }
    }
}

// ---------------- finalize ----------------
__global__ void finalize_kernel(const float* __restrict__ phi_scale,
                                const float* __restrict__ phi_bias,
                                float* __restrict__ out)
{
    const int b = blockIdx.x;
    const int tid = threadIdx.x;

    float lw = 0.f, lp = 0.f;
    for (int i = tid; i < 2048; i += 256)
        lw += sqrtf(g_sumsq[b * 2048 + i]);
#pragma unroll
    for (int h = 0; h < 4; h++) {
        int base = ROWS_WHOLE + h * ROWS_WHOLE + b * 2048;
        for (int i = tid; i < 2048; i += 256)
            lp += sqrtf(g_sumsq[base + i]);
    }

    __shared__ float sw[256];
    __shared__ float sp[256];
    sw[tid] = lw; sp[tid] = lp;
    __syncthreads();
    for (int s = 128; s > 0; s >>= 1) {
        if (tid < s) { sw[tid] += sw[tid + s]; sp[tid] += sp[tid + s]; }
        __syncthreads();
    }
    if (tid == 0) {
        float w = sw[0] / 2048.0f;
        float p = sp[0] / 8192.0f;
        float raw = (w - p) / (w + 1e-8f);
        float phi = phi_scale[0] * raw + phi_bias[0];
        out[b] = fminf(fmaxf(phi, 0.0f), 1.0f);
    }
}

extern "C" void kernel_launch(void* const* d_in, const int* in_sizes, int n_in,
                              void* d_out, int out_size)
{
    const float* cur  = (const float*)d_in[0];   // [4,2048,2048]
    const float* hist = (const float*)d_in[1];   // [4,4,2048,2048]
    const float* Ww   = (const float*)d_in[2];   // [1024,2048]
    const float* bw   = (const float*)d_in[3];   // [1024]
    const float* Wp   = (const float*)d_in[4];   // [1024,2048]
    const float* bp   = (const float*)d_in[5];   // [1024]
    const float* ps   = (const float*)d_in[6];
    const float* pb   = (const float*)d_in[7];
    float* out = (float*)d_out;                  // [4]

    cudaFuncSetAttribute(gemm_fp16x2_kernel,
                         cudaFuncAttributeMaxDynamicSharedMemorySize, SMEM_BYTES);

    zero_kernel<<<(ROWS_TOTAL + 255) / 256, 256>>>();

    gemm_fp16x2_kernel<<<dim3(N_DIM / BN, MB_TOTAL), 256, SMEM_BYTES>>>(
        cur, hist, Ww, bw, Wp, bp);

    finalize_kernel<<<4, 256>>>(ps, pb, out);
}

// round 17
// speedup vs baseline: 1.0505x; 1.0505x over previous
#include <cuda_runtime.h>
#include <cuda_fp16.h>
#include <cstdint>

// ---------------- problem constants ----------------
#define K_DIM       2048
#define N_DIM       1024
#define ROWS_WHOLE  8192
#define ROWS_PARTS  32768
#define ROWS_TOTAL  40960
#define MB_WHOLE    64
#define MB_TOTAL    320

// ---------------- tile config (R11 architecture, frozen) ----------------
#define BM 128
#define BN 128
#define BK 16
#define NCHUNK (K_DIM / BK)        // 128
#define SH 24                      // halves per smem row (48B stride, conflict-free)

#define TERM_H   (BM * SH)
#define AH0_B    0
#define AH1_B    (TERM_H * 2)
#define BH0_B    (2 * TERM_H * 2)
#define BH1_B    (3 * TERM_H * 2)
#define STAGE_B  (4 * TERM_H * 2)      // 24576 bytes per stage
#define BIAS_B   (2 * STAGE_B)
#define SMEM_BYTES (BIAS_B + BN * 4)   // 49664

__device__ float g_sumsq[ROWS_TOTAL];
__device__ float g_w[4];
__device__ float g_p[4];

// ---------------- helpers ----------------
__device__ __forceinline__ void mma16(float* c,
                                      uint32_t a0, uint32_t a1, uint32_t a2, uint32_t a3,
                                      uint32_t b0, uint32_t b1) {
    asm volatile(
        "mma.sync.aligned.m16n8k16.row.col.f32.f16.f16.f32 "
        "{%0,%1,%2,%3}, {%4,%5,%6,%7}, {%8,%9}, {%0,%1,%2,%3};"
        : "+f"(c[0]), "+f"(c[1]), "+f"(c[2]), "+f"(c[3])
        : "r"(a0), "r"(a1), "r"(a2), "r"(a3), "r"(b0), "r"(b1));
}

// split 8 consecutive-k floats into packed fp16 h0 and residual h1
__device__ __forceinline__ void split8(float4 v0, float4 v1, uint4& H0, uint4& H1) {
    __half2 p0 = __floats2half2_rn(v0.x, v0.y);
    __half2 p1 = __floats2half2_rn(v0.z, v0.w);
    __half2 p2 = __floats2half2_rn(v1.x, v1.y);
    __half2 p3 = __floats2half2_rn(v1.z, v1.w);
    float2 q0 = __half22float2(p0);
    float2 q1 = __half22float2(p1);
    float2 q2 = __half22float2(p2);
    float2 q3 = __half22float2(p3);
    __half2 r0 = __floats2half2_rn(v0.x - q0.x, v0.y - q0.y);
    __half2 r1 = __floats2half2_rn(v0.z - q1.x, v0.w - q1.y);
    __half2 r2 = __floats2half2_rn(v1.x - q2.x, v1.y - q2.y);
    __half2 r3 = __floats2half2_rn(v1.z - q3.x, v1.w - q3.y);
    H0 = make_uint4(*(uint32_t*)&p0, *(uint32_t*)&p1, *(uint32_t*)&p2, *(uint32_t*)&p3);
    H1 = make_uint4(*(uint32_t*)&r0, *(uint32_t*)&r1, *(uint32_t*)&r2, *(uint32_t*)&r3);
}

__global__ void zero_kernel() {
    int i = blockIdx.x * 256 + threadIdx.x;
    if (i < ROWS_TOTAL) g_sumsq[i] = 0.0f;
    if (i < 4) { g_w[i] = 0.0f; g_p[i] = 0.0f; }
}

// ---------------- merged fp16x2-split GEMM + row sum-of-squares (R11) ----------------
__global__ __launch_bounds__(256, 2)
void gemm_fp16x2_kernel(const float* __restrict__ Acur,
                        const float* __restrict__ Ahist,
                        const float* __restrict__ Ww,
                        const float* __restrict__ bw,
                        const float* __restrict__ Wp,
                        const float* __restrict__ bp)
{
    extern __shared__ __align__(16) char smem[];
    const int tid = threadIdx.x;
    const int wid = tid >> 5;
    const int lid = tid & 31;
    const int wm  = wid >> 2;
    const int wn  = wid & 3;
    const int r   = lid >> 2;
    const int cq  = lid & 3;
    const int by  = blockIdx.y;
    const int n0  = blockIdx.x * BN;

    const bool is_whole = (by < MB_WHOLE);
    const float* A    = is_whole ? Acur : Ahist;
    const float* W    = is_whole ? Ww   : Wp;
    const float* bias = is_whole ? bw   : bp;
    const int m0      = (is_whole ? by : (by - MB_WHOLE)) * BM;
    const int row_off = is_whole ? 0 : ROWS_WHOLE;

    float* sbias = (float*)(smem + BIAS_B);
    if (tid < BN) sbias[tid] = bias[n0 + tid];

    const int ar = tid >> 1;
    const int ac = (tid & 1) << 3;
    const float* Aptr = A + (size_t)(m0 + ar) * K_DIM + ac;
    const float* Wptr = W + (size_t)(n0 + ar) * K_DIM + ac;
    const uint32_t s_off = (uint32_t)ar * (SH * 2) + (uint32_t)ac * 2;

    float acc[4][4][4];
#pragma unroll
    for (int i = 0; i < 4; i++)
#pragma unroll
        for (int j = 0; j < 4; j++)
#pragma unroll
            for (int q = 0; q < 4; q++) acc[i][j][q] = 0.f;

    float4 av0, av1, bv0, bv1;

#define LOADCHUNK(kc) do { \
        const float* ap_ = Aptr + (size_t)(kc) * BK; \
        av0 = *(const float4*)ap_;  av1 = *(const float4*)(ap_ + 4); \
        const float* wp_ = Wptr + (size_t)(kc) * BK; \
        bv0 = *(const float4*)wp_;  bv1 = *(const float4*)(wp_ + 4); \
    } while (0)

#define STORESTAGE(s) do { \
        char* st_ = smem + (s) * STAGE_B; \
        uint4 H0_, H1_; \
        split8(av0, av1, H0_, H1_); \
        *(uint4*)(st_ + AH0_B + s_off) = H0_; \
        *(uint4*)(st_ + AH1_B + s_off) = H1_; \
        split8(bv0, bv1, H0_, H1_); \
        *(uint4*)(st_ + BH0_B + s_off) = H0_; \
        *(uint4*)(st_ + BH1_B + s_off) = H1_; \
    } while (0)

    LOADCHUNK(0);
    STORESTAGE(0);
    LOADCHUNK(1);
    __syncthreads();

    for (int kc = 0; kc < NCHUNK; kc++) {
        const char* st = smem + (kc & 1) * STAGE_B;

        uint32_t b0h[4], b1h[4], b0l[4], b1l[4];
#pragma unroll
        for (int nf = 0; nf < 4; nf++) {
            const int off = ((wn * 32 + nf * 8 + r) * SH + 2 * cq) * 2;
            b0h[nf] = *(const uint32_t*)(st + BH0_B + off);
            b1h[nf] = *(const uint32_t*)(st + BH0_B + off + 16);
            b0l[nf] = *(const uint32_t*)(st + BH1_B + off);
            b1l[nf] = *(const uint32_t*)(st + BH1_B + off + 16);
        }

#pragma unroll
        for (int mf = 0; mf < 4; mf++) {
            const int off0 = ((wm * 64 + mf * 16 + r) * SH + 2 * cq) * 2;
            const int off1 = off0 + 8 * SH * 2;
            uint32_t ah0 = *(const uint32_t*)(st + AH0_B + off0);
            uint32_t ah1 = *(const uint32_t*)(st + AH0_B + off1);
            uint32_t ah2 = *(const uint32_t*)(st + AH0_B + off0 + 16);
            uint32_t ah3 = *(const uint32_t*)(st + AH0_B + off1 + 16);
            uint32_t al0 = *(const uint32_t*)(st + AH1_B + off0);
            uint32_t al1 = *(const uint32_t*)(st + AH1_B + off1);
            uint32_t al2 = *(const uint32_t*)(st + AH1_B + off0 + 16);
            uint32_t al3 = *(const uint32_t*)(st + AH1_B + off1 + 16);
#pragma unroll
            for (int nf = 0; nf < 4; nf++) {
                mma16(acc[mf][nf], ah0, ah1, ah2, ah3, b0h[nf], b1h[nf]);  // h0*h0
                mma16(acc[mf][nf], ah0, ah1, ah2, ah3, b0l[nf], b1l[nf]);  // h0*h1
                mma16(acc[mf][nf], al0, al1, al2, al3, b0h[nf], b1h[nf]);  // h1*h0
            }
        }

        if (kc + 1 < NCHUNK) {
            STORESTAGE((kc + 1) & 1);
            if (kc + 2 < NCHUNK) LOADCHUNK(kc + 2);
        }
        __syncthreads();
    }

    // ---------------- epilogue: bias, square, per-row reduce, atomic ----------------
#pragma unroll
    for (int mf = 0; mf < 4; mf++) {
        float rs0 = 0.f, rs1 = 0.f;
#pragma unroll
        for (int nf = 0; nf < 4; nf++) {
            const int nc = wn * 32 + nf * 8 + 2 * cq;
            float b0 = sbias[nc], b1 = sbias[nc + 1];
            float v;
            v = acc[mf][nf][0] + b0; rs0 += v * v;
            v = acc[mf][nf][1] + b1; rs0 += v * v;
            v = acc[mf][nf][2] + b0; rs1 += v * v;
            v = acc[mf][nf][3] + b1; rs1 += v * v;
        }
        rs0 += __shfl_xor_sync(0xffffffffu, rs0, 1);
        rs0 += __shfl_xor_sync(0xffffffffu, rs0, 2);
        rs1 += __shfl_xor_sync(0xffffffffu, rs1, 1);
        rs1 += __shfl_xor_sync(0xffffffffu, rs1, 2);
        if (cq == 0) {
            const int mrow = row_off + m0 + wm * 64 + mf * 16 + r;
            atomicAdd(&g_sumsq[mrow],     rs0);
            atomicAdd(&g_sumsq[mrow + 8], rs1);
        }
    }
}

// ---------------- parallel norm-sum partials ----------------
// grid (4, 5): block (b, g). g==0 -> whole region of batch b; g in 1..4 ->
// history slice h=g-1 of batch b. Each region is 2048 contiguous rows.
__global__ void normsum_kernel()
{
    const int b = blockIdx.x;
    const int g = blockIdx.y;
    const int tid = threadIdx.x;

    const int base = (g == 0) ? (b * 2048)
                              : (ROWS_WHOLE + (g - 1) * ROWS_WHOLE + b * 2048);

    float s = 0.f;
    for (int i = tid; i < 2048; i += 256)
        s += sqrtf(g_sumsq[base + i]);

    __shared__ float red[256];
    red[tid] = s;
    __syncthreads();
    for (int st = 128; st > 0; st >>= 1) {
        if (tid < st) red[tid] += red[tid + st];
        __syncthreads();
    }
    if (tid == 0) {
        if (g == 0) atomicAdd(&g_w[b], red[0]);
        else        atomicAdd(&g_p[b], red[0]);
    }
}

// ---------------- phi ----------------
__global__ void phi_kernel(const float* __restrict__ phi_scale,
                           const float* __restrict__ phi_bias,
                           float* __restrict__ out)
{
    const int b = threadIdx.x;
    if (b < 4) {
        float w = g_w[b] / 2048.0f;
        float p = g_p[b] / 8192.0f;
        float raw = (w - p) / (w + 1e-8f);
        float phi = phi_scale[0] * raw + phi_bias[0];
        out[b] = fminf(fmaxf(phi, 0.0f), 1.0f);
    }
}

extern "C" void kernel_launch(void* const* d_in, const int* in_sizes, int n_in,
                              void* d_out, int out_size)
{
    const float* cur  = (const float*)d_in[0];   // [4,2048,2048]
    const float* hist = (const float*)d_in[1];   // [4,4,2048,2048]
    const float* Ww   = (const float*)d_in[2];   // [1024,2048]
    const float* bw   = (const float*)d_in[3];   // [1024]
    const float* Wp   = (const float*)d_in[4];   // [1024,2048]
    const float* bp   = (const float*)d_in[5];   // [1024]
    const float* ps   = (const float*)d_in[6];
    const float* pb   = (const float*)d_in[7];
    float* out = (float*)d_out;                  // [4]

    cudaFuncSetAttribute(gemm_fp16x2_kernel,
                         cudaFuncAttributeMaxDynamicSharedMemorySize, SMEM_BYTES);

    zero_kernel<<<(ROWS_TOTAL + 255) / 256, 256>>>();

    gemm_fp16x2_kernel<<<dim3(N_DIM / BN, MB_TOTAL), 256, SMEM_BYTES>>>(
        cur, hist, Ww, bw, Wp, bp);

    normsum_kernel<<<dim3(4, 5), 256>>>();
    phi_kernel<<<1, 4>>>(ps, pb, out);
}